// round 17
// baseline (speedup 1.0000x reference)
#include <cuda_runtime.h>
#include <cstdint>

#define NN 50000
#define NE 800000
#define TM 384                // nodes per block tile
#define XPAD 132              // smem X row stride (floats); 132&31=4 -> no bank clash
#define KC 16                 // GEMM k-chunk
#define WPAD 100              // Ws row stride (400B, 16B-aligned)
#define NTILES 131            // ceil(NN/TM)
#define NB 148
#define NT 768
#define GSZ (NB * NT)
#define CHUNK 338             // ceil(NN/NB)
#define SMEM_FLOATS (TM * XPAD + KC * WPAD)
#define SMEM_BYTES (SMEM_FLOATS * 4)

// ---------------- scratch (device globals; no allocation allowed) ----------
__device__ float g_P[NN * 192];       // ping-pong: A = [0, NN*96), B = [NN*96, NN*192)
__device__ int   g_cnt[NN];
__device__ int   g_cursor[NN];
__device__ int   g_rowptr[NN + 1];
__device__ int2  g_edge[NE];
__device__ int   g_bsum[NB];
__device__ unsigned g_bar_count;
__device__ unsigned g_bar_gen;

// ---------------- software grid barrier ------------------------------------
__device__ __forceinline__ void grid_barrier() {
    __syncthreads();
    if (threadIdx.x == 0) {
        unsigned gen = *(volatile unsigned*)&g_bar_gen;
        __threadfence();
        if (atomicAdd(&g_bar_count, 1u) == NB - 1) {
            g_bar_count = 0u;
            __threadfence();
            *(volatile unsigned*)&g_bar_gen = gen + 1u;
        } else {
            while (*(volatile unsigned*)&g_bar_gen == gen) __nanosleep(64);
        }
    }
    __syncthreads();
}

// ---------------- gather tile into smem: S[384][XPAD] = (A_hat * in)[tile] --
// warp per node (16 nodes/warp); CIN=128: 32 lanes, CIN=96: 24 lanes.
template <int CIN>
__device__ __forceinline__ void gather_tile_smem(const float* __restrict__ in,
                                                 int tile, float* __restrict__ S) {
    const int lane = threadIdx.x & 31;
    const int warp = threadIdx.x >> 5;          // 0..23
    const int node0 = tile * TM;
    const int NL = CIN / 4;                     // float4 per row (32 or 24)
    const float4* __restrict__ h4 = (const float4*)in;

    for (int it = 0; it < TM / 24; it++) {      // 16 nodes per warp
        const int nl = warp * (TM / 24) + it;
        const int node = node0 + nl;
        if (node < NN && lane < NL) {
            const int beg = __ldcg(&g_rowptr[node]);
            const int end = __ldcg(&g_rowptr[node + 1]);

            float4 acc = make_float4(0.f, 0.f, 0.f, 0.f);
            float4 acc2 = make_float4(0.f, 0.f, 0.f, 0.f);
            int e = beg;
            for (; e + 8 <= end; e += 8) {
                int2 E[8];
#pragma unroll
                for (int j = 0; j < 8; j++) E[j] = __ldcg(&g_edge[e + j]);
                float4 v[8];
#pragma unroll
                for (int j = 0; j < 8; j++)
                    v[j] = __ldcg(h4 + (size_t)E[j].x * NL + lane);
#pragma unroll
                for (int j = 0; j < 4; j++) {
                    float w = __int_as_float(E[j].y);
                    acc.x += v[j].x * w; acc.y += v[j].y * w;
                    acc.z += v[j].z * w; acc.w += v[j].w * w;
                }
#pragma unroll
                for (int j = 4; j < 8; j++) {
                    float w = __int_as_float(E[j].y);
                    acc2.x += v[j].x * w; acc2.y += v[j].y * w;
                    acc2.z += v[j].z * w; acc2.w += v[j].w * w;
                }
            }
            for (; e + 4 <= end; e += 4) {
                int2 E[4];
#pragma unroll
                for (int j = 0; j < 4; j++) E[j] = __ldcg(&g_edge[e + j]);
                float4 v[4];
#pragma unroll
                for (int j = 0; j < 4; j++)
                    v[j] = __ldcg(h4 + (size_t)E[j].x * NL + lane);
#pragma unroll
                for (int j = 0; j < 4; j++) {
                    float w = __int_as_float(E[j].y);
                    acc.x += v[j].x * w; acc.y += v[j].y * w;
                    acc.z += v[j].z * w; acc.w += v[j].w * w;
                }
            }
            for (; e < end; e++) {
                int2 E = __ldcg(&g_edge[e]);
                float4 v = __ldcg(h4 + (size_t)E.x * NL + lane);
                float w = __int_as_float(E.y);
                acc.x += v.x * w; acc.y += v.y * w; acc.z += v.z * w; acc.w += v.w * w;
            }
            acc.x += acc2.x; acc.y += acc2.y; acc.z += acc2.z; acc.w += acc2.w;

            const float dii = 1.0f / (float)(__ldcg(&g_cnt[node]) + 1);
            float4 hv = __ldcg(h4 + (size_t)node * NL + lane);
            acc.x += hv.x * dii; acc.y += hv.y * dii;
            acc.z += hv.z * dii; acc.w += hv.w * dii;

            *(float4*)&S[nl * XPAD + lane * 4] = acc;
        }
    }
}

// ---------------- GEMM from smem tile: out[tile] = relu?(S @ W + b) ---------
// thread: cg = tid&7 (12 ch), ng = tid>>3 (4 nodes). f32x2 accumulators.
__device__ __forceinline__ void gemm_tile_smem(const float* __restrict__ S,
                                               const float* __restrict__ W,
                                               const float* __restrict__ b,
                                               float* __restrict__ out,
                                               int cin, int tile, int relu,
                                               float* __restrict__ Ws) {
    const int tid = threadIdx.x;
    const int cg = tid & 7;
    const int ng = tid >> 3;
    const int node0 = tile * TM;

    const int wr = (tid < 384) ? (tid / 24) : 0;
    const int wcq = (tid < 384) ? (tid % 24) : 0;

    unsigned long long acc2[4][6];
#pragma unroll
    for (int i = 0; i < 4; i++)
#pragma unroll
        for (int j = 0; j < 6; j++) acc2[i][j] = 0ull;

    const int nkc = cin >> 4;

    float4 pw;
    if (tid < 384)
        pw = ((const float4*)(W + (size_t)wr * 96))[wcq];

    for (int kc = 0; kc < nkc; kc++) {
        if (tid < 384)
            *(float4*)&Ws[wr * WPAD + wcq * 4] = pw;
        __syncthreads();

        if (kc + 1 < nkc) {
            const int koff = (kc + 1) * KC;
            if (tid < 384)
                pw = ((const float4*)(W + (size_t)(koff + wr) * 96))[wcq];
        }

        const float* Sk = S + kc * KC;
#pragma unroll
        for (int k = 0; k < KC; k++) {
            const unsigned long long* wp =
                (const unsigned long long*)&Ws[k * WPAD + cg * 12];
            unsigned long long w[6];
#pragma unroll
            for (int j = 0; j < 6; j++) w[j] = wp[j];
#pragma unroll
            for (int i = 0; i < 4; i++) {
                unsigned xb = __float_as_uint(Sk[(ng * 4 + i) * XPAD + k]);
                unsigned long long xx;
                asm("mov.b64 %0, {%1, %1};" : "=l"(xx) : "r"(xb));
#pragma unroll
                for (int j = 0; j < 6; j++)
                    asm("fma.rn.f32x2 %0, %1, %2, %0;"
                        : "+l"(acc2[i][j]) : "l"(xx), "l"(w[j]));
            }
        }
        __syncthreads();
    }

    // epilogue: + bias, relu, store
    float bb[12];
#pragma unroll
    for (int t = 0; t < 12; t++) bb[t] = b[cg * 12 + t];

#pragma unroll
    for (int i = 0; i < 4; i++) {
        int nd = node0 + ng * 4 + i;
        if (nd < NN) {
            float r[12];
#pragma unroll
            for (int j = 0; j < 6; j++) {
                unsigned lo, hi;
                asm("mov.b64 {%0, %1}, %2;" : "=r"(lo), "=r"(hi) : "l"(acc2[i][j]));
                r[2 * j]     = __uint_as_float(lo) + bb[2 * j];
                r[2 * j + 1] = __uint_as_float(hi) + bb[2 * j + 1];
            }
            if (relu) {
#pragma unroll
                for (int t = 0; t < 12; t++) r[t] = fmaxf(r[t], 0.f);
            }
            float* o = out + (size_t)nd * 96 + cg * 12;
            *(float4*)(o)     = make_float4(r[0], r[1], r[2], r[3]);
            *(float4*)(o + 4) = make_float4(r[4], r[5], r[6], r[7]);
            *(float4*)(o + 8) = make_float4(r[8], r[9], r[10], r[11]);
        }
    }
}

// ---------------- the one persistent kernel --------------------------------
__global__ __launch_bounds__(NT, 1) void gcn_mega_kernel(
    const float* __restrict__ x, const int* __restrict__ ei,
    const float* __restrict__ W1, const float* __restrict__ b1,
    const float* __restrict__ W2, const float* __restrict__ b2,
    const float* __restrict__ W3, const float* __restrict__ b3,
    const float* __restrict__ W4, const float* __restrict__ b4,
    float* __restrict__ out)
{
    extern __shared__ float smem[];
    float* S  = smem;                       // [TM][XPAD]
    float* Ws = smem + TM * XPAD;           // [KC][WPAD]
    int* sc = (int*)smem;                   // scan scratch

    const int tid = threadIdx.x;
    const int gtid = blockIdx.x * NT + tid;

    // P0: zero cnt + cursor
    for (int i = gtid; i < NN; i += GSZ) { g_cnt[i] = 0; g_cursor[i] = 0; }
    grid_barrier();

    // P1: degree count
    for (int e = gtid; e < NE; e += GSZ) atomicAdd(&g_cnt[ei[NE + e]], 1);
    grid_barrier();

    // P2a: block exclusive scan (CHUNK=338 <= NT)
    const int base = blockIdx.x * CHUNK;
    const int lim = min(base + CHUNK, NN);
    const int myi = base + tid;
    int mysum = (myi < lim) ? __ldcg(&g_cnt[myi]) : 0;
    sc[tid] = mysum;
    __syncthreads();
    for (int off = 1; off < NT; off <<= 1) {
        int v = (tid >= off) ? sc[tid - off] : 0;
        __syncthreads();
        sc[tid] += v;
        __syncthreads();
    }
    int myexcl = sc[tid] - mysum;
    if (tid == NT - 1) g_bsum[blockIdx.x] = sc[tid];
    grid_barrier();

    // P2b: warp scan of block sums
    if (blockIdx.x == 0 && tid < 32) {
        int carry = 0;
        for (int b0 = 0; b0 < NB; b0 += 32) {
            int i = b0 + tid;
            int v = (i < NB) ? __ldcg(&g_bsum[i]) : 0;
            int orig = v;
#pragma unroll
            for (int o = 1; o < 32; o <<= 1) {
                int t = __shfl_up_sync(0xffffffffu, v, o);
                if ((tid & 31) >= o) v += t;
            }
            if (i < NB) g_bsum[i] = carry + v - orig;
            carry += __shfl_sync(0xffffffffu, v, 31);
        }
        if (tid == 0) g_rowptr[NN] = carry;
    }
    grid_barrier();

    // P2c: final rowptr
    if (myi < lim) g_rowptr[myi] = __ldcg(&g_bsum[blockIdx.x]) + myexcl;
    grid_barrier();

    // P3: fill CSR with precomputed edge weight
    for (int e = gtid; e < NE; e += GSZ) {
        int s = ei[e];
        int d = ei[NE + e];
        float w = rsqrtf((float)((__ldcg(&g_cnt[s]) + 1) * (__ldcg(&g_cnt[d]) + 1)));
        int pos = atomicAdd(&g_cursor[d], 1);
        g_edge[__ldcg(&g_rowptr[d]) + pos] = make_int2(s, __float_as_int(w));
    }
    grid_barrier();

    // layers: gather-first (A_hat * in) into smem, then GEMM from smem.
    // ping-pong: A = g_P, B = g_P + NN*96
    float* A = g_P;
    float* B = g_P + (size_t)NN * 96;
    const int tile = blockIdx.x;

    // layer 1: x (cin 128) -> A
    if (tile < NTILES) {
        gather_tile_smem<128>(x, tile, S);
        __syncthreads();
        gemm_tile_smem(S, W1, b1, A, 128, tile, 1, Ws);
    }
    grid_barrier();

    // layer 2: A -> B
    if (tile < NTILES) {
        gather_tile_smem<96>(A, tile, S);
        __syncthreads();
        gemm_tile_smem(S, W2, b2, B, 96, tile, 1, Ws);
    }
    grid_barrier();

    // layer 3: B -> A
    if (tile < NTILES) {
        gather_tile_smem<96>(B, tile, S);
        __syncthreads();
        gemm_tile_smem(S, W3, b3, A, 96, tile, 1, Ws);
    }
    grid_barrier();

    // layer 4 (no relu): A -> out
    if (tile < NTILES) {
        gather_tile_smem<96>(A, tile, S);
        __syncthreads();
        gemm_tile_smem(S, W4, b4, out, 96, tile, 0, Ws);
    }
}

// ---------------- launch ----------------------------------------------------
extern "C" void kernel_launch(void* const* d_in, const int* in_sizes, int n_in,
                              void* d_out, int out_size) {
    const float* x  = (const float*)d_in[0];
    const int*   ei = (const int*)d_in[1];   // int32 (JAX demotes int64)
    const float* W1 = (const float*)d_in[2];
    const float* b1 = (const float*)d_in[3];
    const float* W2 = (const float*)d_in[4];
    const float* b2 = (const float*)d_in[5];
    const float* W3 = (const float*)d_in[6];
    const float* b3 = (const float*)d_in[7];
    const float* W4 = (const float*)d_in[8];
    const float* b4 = (const float*)d_in[9];
    float* out = (float*)d_out;

    cudaFuncSetAttribute(gcn_mega_kernel,
                         cudaFuncAttributeMaxDynamicSharedMemorySize, SMEM_BYTES);
    gcn_mega_kernel<<<NB, NT, SMEM_BYTES>>>(x, ei, W1, b1, W2, b2, W3, b3, W4, b4, out);
}